// round 2
// baseline (speedup 1.0000x reference)
#include <cuda_runtime.h>

#define BB 8192
#define TT 256
#define FF 16
#define HH 8
#define FUT 8

__device__ __forceinline__ float tanhm(float x) {
    float y;
    asm("tanh.approx.f32 %0, %1;" : "=f"(y) : "f"(x));
    return y;
}
__device__ __forceinline__ float sigm(float x) {
    // sigmoid(x) = 0.5*tanh(0.5x) + 0.5  (1 MUFU + 1 FMUL + 1 FFMA)
    return fmaf(0.5f, tanhm(0.5f * x), 0.5f);
}

__global__ __launch_bounds__(64) void LSTM_91122026152229_kernel(
    const float* __restrict__ past,   // [B,T,F]
    const float* __restrict__ fut,    // [B,FUT]
    const float* __restrict__ W1, const float* __restrict__ U1, const float* __restrict__ b1,
    const float* __restrict__ W2, const float* __restrict__ U2, const float* __restrict__ b2,
    const float* __restrict__ Wd1, const float* __restrict__ bd1,
    const float* __restrict__ Wd2, const float* __restrict__ bd2,
    const float* __restrict__ Wo, const float* __restrict__ bo,
    float* __restrict__ out)          // [B,4]
{
    // Gate-packed weight tiles: [k][u] -> float4 {i,f,g,o}
    __shared__ float4 sW1v[FF * HH];          // 16*8 float4 = 2 KB
    __shared__ float4 sU1v[HH * HH];          // 1 KB
    __shared__ float4 sWU2v[2 * HH * HH];     // rows 0..7: W2, 8..15: U2 (2 KB)
    __shared__ float sb1[32], sb2[32];
    __shared__ float sWd1[16 * 8];
    __shared__ float sWd2[8 * 8];
    __shared__ float sWo[8 * 4];
    __shared__ float sbd1[8], sbd2[8], sbo[4];

    const int tid = threadIdx.x;
    float* sW1f  = (float*)sW1v;
    float* sU1f  = (float*)sU1v;
    float* sWU2f = (float*)sWU2v;
    // repack: src idx i = k*32 + g*8 + u  ->  dst = k*32 + u*4 + g
    for (int i = tid; i < FF * 32; i += 64) {
        int k = i >> 5, r = i & 31, g = r >> 3, u = r & 7;
        sW1f[k * 32 + u * 4 + g] = W1[i];
    }
    for (int i = tid; i < HH * 32; i += 64) {
        int k = i >> 5, r = i & 31, g = r >> 3, u = r & 7;
        sU1f[k * 32 + u * 4 + g]          = U1[i];
        sWU2f[k * 32 + u * 4 + g]         = W2[i];
        sWU2f[(k + 8) * 32 + u * 4 + g]   = U2[i];
    }
    for (int i = tid; i < 32; i += 64) { sb1[i] = b1[i]; sb2[i] = b2[i]; }
    for (int i = tid; i < 128; i += 64) sWd1[i] = Wd1[i];
    if (tid < 64) sWd2[tid] = Wd2[tid];
    if (tid < 32) sWo[tid] = Wo[tid];
    if (tid < 8)  { sbd1[tid] = bd1[tid]; sbd2[tid] = bd2[tid]; }
    if (tid < 4)  sbo[tid] = bo[tid];
    __syncthreads();

    // 8 threads per batch element; thread owns hidden unit u
    const int g    = blockIdx.x * 64 + tid;
    const int e    = g >> 3;
    const int u    = g & 7;
    const int lane = tid & 31;
    const int base8 = lane & 24;

    const float4* __restrict__ xp = (const float4*)(past + (size_t)e * (TT * FF));

    float h1 = 0.f, c1 = 0.f, h2 = 0.f, c2 = 0.f;
    float h1v[8], h2v[8];
    #pragma unroll
    for (int j = 0; j < 8; j++) { h1v[j] = 0.f; h2v[j] = 0.f; }

    const float bi1 = sb1[u], bf1 = sb1[u + 8], bg1 = sb1[u + 16], bq1 = sb1[u + 24];
    const float bi2 = sb2[u], bf2 = sb2[u + 8], bg2 = sb2[u + 16], bq2 = sb2[u + 24];

    for (int t = 0; t < TT; t++) {
        const float4 xa = xp[t * 4 + 0];
        const float4 xb = xp[t * 4 + 1];
        const float4 xc = xp[t * 4 + 2];
        const float4 xd = xp[t * 4 + 3];
        const float xr[16] = { xa.x, xa.y, xa.z, xa.w,  xb.x, xb.y, xb.z, xb.w,
                               xc.x, xc.y, xc.z, xc.w,  xd.x, xd.y, xd.z, xd.w };

        // ---- layer 1 ----
        float zi = bi1, zf = bf1, zg = bg1, zo = bq1;
        #pragma unroll
        for (int k = 0; k < 16; k++) {
            const float4 w = sW1v[k * 8 + u];
            const float xv = xr[k];
            zi = fmaf(xv, w.x, zi);
            zf = fmaf(xv, w.y, zf);
            zg = fmaf(xv, w.z, zg);
            zo = fmaf(xv, w.w, zo);
        }
        #pragma unroll
        for (int k = 0; k < 8; k++) {
            const float4 w = sU1v[k * 8 + u];
            const float hk = h1v[k];
            zi = fmaf(hk, w.x, zi);
            zf = fmaf(hk, w.y, zf);
            zg = fmaf(hk, w.z, zg);
            zo = fmaf(hk, w.w, zo);
        }
        c1 = sigm(zf) * c1 + sigm(zi) * tanhm(zg);
        h1 = sigm(zo) * tanhm(c1);

        // broadcast new h1 to the 8-lane group
        #pragma unroll
        for (int j = 0; j < 8; j++)
            h1v[j] = __shfl_sync(0xffffffffu, h1, base8 + j);

        // ---- layer 2 ----
        float yi = bi2, yf = bf2, yg = bg2, yo = bq2;
        #pragma unroll
        for (int k = 0; k < 8; k++) {
            const float4 w = sWU2v[k * 8 + u];
            const float hk = h1v[k];
            yi = fmaf(hk, w.x, yi);
            yf = fmaf(hk, w.y, yf);
            yg = fmaf(hk, w.z, yg);
            yo = fmaf(hk, w.w, yo);
        }
        #pragma unroll
        for (int k = 0; k < 8; k++) {
            const float4 w = sWU2v[(k + 8) * 8 + u];
            const float hk = h2v[k];
            yi = fmaf(hk, w.x, yi);
            yf = fmaf(hk, w.y, yf);
            yg = fmaf(hk, w.z, yg);
            yo = fmaf(hk, w.w, yo);
        }
        c2 = sigm(yf) * c2 + sigm(yi) * tanhm(yg);
        h2 = sigm(yo) * tanhm(c2);

        // broadcast new h2 to the 8-lane group
        #pragma unroll
        for (int j = 0; j < 8; j++)
            h2v[j] = __shfl_sync(0xffffffffu, h2, base8 + j);
    }

    // ---- MLP head: concat(h2, fut) -> 8 relu -> 8 relu -> 4 ----
    float d1 = sbd1[u];
    #pragma unroll
    for (int k = 0; k < 8; k++)
        d1 = fmaf(h2v[k], sWd1[k * 8 + u], d1);
    const float* __restrict__ fp = fut + (size_t)e * FUT;
    #pragma unroll
    for (int k = 0; k < 8; k++)
        d1 = fmaf(fp[k], sWd1[(8 + k) * 8 + u], d1);
    d1 = fmaxf(d1, 0.f);

    float d2 = sbd2[u];
    #pragma unroll
    for (int k = 0; k < 8; k++) {
        const float d1k = __shfl_sync(0xffffffffu, d1, base8 + k);
        d2 = fmaf(d1k, sWd2[k * 8 + u], d2);
    }
    d2 = fmaxf(d2, 0.f);

    float o = (u < 4) ? sbo[u] : 0.f;
    #pragma unroll
    for (int k = 0; k < 8; k++) {
        const float d2k = __shfl_sync(0xffffffffu, d2, base8 + k);
        if (u < 4) o = fmaf(d2k, sWo[k * 4 + u], o);
    }
    if (u < 4) out[(size_t)e * 4 + u] = o;
}

extern "C" void kernel_launch(void* const* d_in, const int* in_sizes, int n_in,
                              void* d_out, int out_size) {
    const float* past = (const float*)d_in[1];
    const float* fut  = (const float*)d_in[2];
    const float* W1   = (const float*)d_in[3];
    const float* U1   = (const float*)d_in[4];
    const float* b1   = (const float*)d_in[5];
    const float* W2   = (const float*)d_in[6];
    const float* U2   = (const float*)d_in[7];
    const float* b2   = (const float*)d_in[8];
    const float* Wd1  = (const float*)d_in[9];
    const float* bd1  = (const float*)d_in[10];
    const float* Wd2  = (const float*)d_in[11];
    const float* bd2  = (const float*)d_in[12];
    const float* Wo   = (const float*)d_in[13];
    const float* bo   = (const float*)d_in[14];

    // 65536 threads, 8 per batch element; small blocks for wave balance
    LSTM_91122026152229_kernel<<<(BB * HH) / 64, 64>>>(
        past, fut, W1, U1, b1, W2, U2, b2, Wd1, bd1, Wd2, bd2, Wo, bo,
        (float*)d_out);
}

// round 3
// speedup vs baseline: 1.3156x; 1.3156x over previous
#include <cuda_runtime.h>

#define BB 8192
#define TT 256
#define FF 16
#define HH 8
#define FUT 8

typedef unsigned long long u64;

__device__ __forceinline__ float tanhm(float x) {
    float y;
    asm("tanh.approx.f32 %0, %1;" : "=f"(y) : "f"(x));
    return y;
}
__device__ __forceinline__ float sigm(float x) {
    // sigmoid(x) = 0.5*tanh(0.5x) + 0.5
    return fmaf(0.5f, tanhm(0.5f * x), 0.5f);
}
__device__ __forceinline__ u64 ffma2(u64 a, u64 b, u64 c) {
    u64 d;
    asm("fma.rn.f32x2 %0, %1, %2, %3;" : "=l"(d) : "l"(a), "l"(b), "l"(c));
    return d;
}
__device__ __forceinline__ u64 pack2(float lo, float hi) {
    u64 r;
    asm("mov.b64 %0, {%1, %2};" : "=l"(r) : "f"(lo), "f"(hi));
    return r;
}
__device__ __forceinline__ float2 unpack2(u64 v) {
    float lo, hi;
    asm("mov.b64 {%0, %1}, %2;" : "=f"(lo), "=f"(hi) : "l"(v));
    return make_float2(lo, hi);
}

// Pairwise-k packed weight tiles in smem.
// For gate-pair arrays: element [k2*8+u] is a ulonglong2 where
//   .x = f32x2 (w_gateA[2k2], w_gateA[2k2+1]),  .y = same for gateB.
// if-array: gateA=i, gateB=f.  go-array: gateA=g, gateB=o.

__global__ __launch_bounds__(128, 4) void LSTM_91122026152229_kernel(
    const float* __restrict__ past,   // [B,T,F]
    const float* __restrict__ fut,    // [B,FUT]
    const float* __restrict__ W1, const float* __restrict__ U1, const float* __restrict__ b1,
    const float* __restrict__ W2, const float* __restrict__ U2, const float* __restrict__ b2,
    const float* __restrict__ Wd1, const float* __restrict__ bd1,
    const float* __restrict__ Wd2, const float* __restrict__ bd2,
    const float* __restrict__ Wo, const float* __restrict__ bo,
    float* __restrict__ out)          // [B,4]
{
    __shared__ ulonglong2 sW1if[8 * 8], sW1go[8 * 8];   // k2=0..7
    __shared__ ulonglong2 sU1if[4 * 8], sU1go[4 * 8];   // k2=0..3
    __shared__ ulonglong2 sW2if[4 * 8], sW2go[4 * 8];
    __shared__ ulonglong2 sU2if[4 * 8], sU2go[4 * 8];

    const int tid = threadIdx.x;

    // ---- repack W1 (512 floats): src i = f*32 + g*8 + u ----
    for (int i = tid; i < 512; i += 128) {
        int f = i >> 5, r = i & 31, g = r >> 3, uu = r & 7;
        int k2 = f >> 1, odd = f & 1;
        float v = W1[i];
        if (g < 2)
            ((float*)sW1if)[((k2 * 8 + uu) << 2) + g * 2 + odd] = v;
        else
            ((float*)sW1go)[((k2 * 8 + uu) << 2) + (g - 2) * 2 + odd] = v;
    }
    // ---- repack U1, W2, U2 (256 floats each): src i = k*32 + g*8 + u ----
    for (int i = tid; i < 256; i += 128) {
        int k = i >> 5, r = i & 31, g = r >> 3, uu = r & 7;
        int k2 = k >> 1, odd = k & 1;
        int fo = ((k2 * 8 + uu) << 2) + ((g & 1) * 2) + odd;  // within if/go array
        float vU1 = U1[i], vW2 = W2[i], vU2 = U2[i];
        if (g < 2) {
            ((float*)sU1if)[fo] = vU1;
            ((float*)sW2if)[fo] = vW2;
            ((float*)sU2if)[fo] = vU2;
        } else {
            ((float*)sU1go)[fo] = vU1;
            ((float*)sW2go)[fo] = vW2;
            ((float*)sU2go)[fo] = vU2;
        }
    }
    __syncthreads();

    // 8 threads per batch element; thread owns hidden unit u
    const int g     = blockIdx.x * 128 + tid;
    const int e     = g >> 3;
    const int u     = g & 7;
    const int lane  = tid & 31;
    const int base8 = lane & 24;

    const ulonglong2* __restrict__ xp2 =
        (const ulonglong2*)(past + (size_t)e * (TT * FF));

    // Per-gate biases (read once from global)
    const float bi1 = b1[u], bf1 = b1[u + 8], bg1 = b1[u + 16], bq1 = b1[u + 24];
    const float bi2 = b2[u], bf2 = b2[u + 8], bg2 = b2[u + 16], bq2 = b2[u + 24];

    float h1 = 0.f, c1 = 0.f, h2 = 0.f, c2 = 0.f;
    u64 hp1[4], hp2[4];
    #pragma unroll
    for (int j = 0; j < 4; j++) { hp1[j] = 0ULL; hp2[j] = 0ULL; }

    #pragma unroll 1
    for (int t = 0; t < TT; t++) {
        // x_t: 16 floats = 8 f32x2 pairs, straight from LDG.128
        const ulonglong2 xA = xp2[t * 4 + 0];
        const ulonglong2 xB = xp2[t * 4 + 1];
        const ulonglong2 xC = xp2[t * 4 + 2];
        const ulonglong2 xD = xp2[t * 4 + 3];
        const u64 xq[8] = { xA.x, xA.y, xB.x, xB.y, xC.x, xC.y, xD.x, xD.y };

        // ---- layer 1 ----
        u64 ai = 0, af = 0, ag = 0, ao = 0;
        #pragma unroll
        for (int k2 = 0; k2 < 8; k2++) {
            const ulonglong2 wif = sW1if[k2 * 8 + u];
            const ulonglong2 wgo = sW1go[k2 * 8 + u];
            const u64 xv = xq[k2];
            ai = ffma2(xv, wif.x, ai);
            af = ffma2(xv, wif.y, af);
            ag = ffma2(xv, wgo.x, ag);
            ao = ffma2(xv, wgo.y, ao);
        }
        #pragma unroll
        for (int k2 = 0; k2 < 4; k2++) {
            const ulonglong2 wif = sU1if[k2 * 8 + u];
            const ulonglong2 wgo = sU1go[k2 * 8 + u];
            const u64 hv = hp1[k2];
            ai = ffma2(hv, wif.x, ai);
            af = ffma2(hv, wif.y, af);
            ag = ffma2(hv, wgo.x, ag);
            ao = ffma2(hv, wgo.y, ao);
        }
        {
            const float2 vi = unpack2(ai), vf = unpack2(af);
            const float2 vg = unpack2(ag), vo = unpack2(ao);
            const float zi = (vi.x + vi.y) + bi1;
            const float zf = (vf.x + vf.y) + bf1;
            const float zg = (vg.x + vg.y) + bg1;
            const float zo = (vo.x + vo.y) + bq1;
            c1 = fmaf(sigm(zf), c1, sigm(zi) * tanhm(zg));
            h1 = sigm(zo) * tanhm(c1);
        }
        // broadcast fresh h1 pairs (used by layer2 now and layer1 next step)
        #pragma unroll
        for (int k2 = 0; k2 < 4; k2++) {
            const float a = __shfl_sync(0xffffffffu, h1, base8 + 2 * k2);
            const float b = __shfl_sync(0xffffffffu, h1, base8 + 2 * k2 + 1);
            hp1[k2] = pack2(a, b);
        }

        // ---- layer 2 ----
        u64 yi = 0, yf = 0, yg = 0, yo = 0;
        #pragma unroll
        for (int k2 = 0; k2 < 4; k2++) {
            const ulonglong2 wif = sW2if[k2 * 8 + u];
            const ulonglong2 wgo = sW2go[k2 * 8 + u];
            const u64 hv = hp1[k2];
            yi = ffma2(hv, wif.x, yi);
            yf = ffma2(hv, wif.y, yf);
            yg = ffma2(hv, wgo.x, yg);
            yo = ffma2(hv, wgo.y, yo);
        }
        #pragma unroll
        for (int k2 = 0; k2 < 4; k2++) {
            const ulonglong2 wif = sU2if[k2 * 8 + u];
            const ulonglong2 wgo = sU2go[k2 * 8 + u];
            const u64 hv = hp2[k2];
            yi = ffma2(hv, wif.x, yi);
            yf = ffma2(hv, wif.y, yf);
            yg = ffma2(hv, wgo.x, yg);
            yo = ffma2(hv, wgo.y, yo);
        }
        {
            const float2 vi = unpack2(yi), vf = unpack2(yf);
            const float2 vg = unpack2(yg), vo = unpack2(yo);
            const float zi = (vi.x + vi.y) + bi2;
            const float zf = (vf.x + vf.y) + bf2;
            const float zg = (vg.x + vg.y) + bg2;
            const float zo = (vo.x + vo.y) + bq2;
            c2 = fmaf(sigm(zf), c2, sigm(zi) * tanhm(zg));
            h2 = sigm(zo) * tanhm(c2);
        }
        // broadcast fresh h2 pairs (used by layer2 next step)
        #pragma unroll
        for (int k2 = 0; k2 < 4; k2++) {
            const float a = __shfl_sync(0xffffffffu, h2, base8 + 2 * k2);
            const float b = __shfl_sync(0xffffffffu, h2, base8 + 2 * k2 + 1);
            hp2[k2] = pack2(a, b);
        }
    }

    // ---- MLP head: concat(h2, fut) -> 8 relu -> 8 relu -> 4 (one-shot, global reads) ----
    float h2s[8];
    #pragma unroll
    for (int k2 = 0; k2 < 4; k2++) {
        const float2 p = unpack2(hp2[k2]);
        h2s[2 * k2] = p.x; h2s[2 * k2 + 1] = p.y;
    }

    float d1 = bd1[u];
    #pragma unroll
    for (int k = 0; k < 8; k++)
        d1 = fmaf(h2s[k], Wd1[k * 8 + u], d1);
    const float* __restrict__ fp = fut + (size_t)e * FUT;
    #pragma unroll
    for (int k = 0; k < 8; k++)
        d1 = fmaf(fp[k], Wd1[(8 + k) * 8 + u], d1);
    d1 = fmaxf(d1, 0.f);

    float d2 = bd2[u];
    #pragma unroll
    for (int k = 0; k < 8; k++) {
        const float d1k = __shfl_sync(0xffffffffu, d1, base8 + k);
        d2 = fmaf(d1k, Wd2[k * 8 + u], d2);
    }
    d2 = fmaxf(d2, 0.f);

    float o = (u < 4) ? bo[u] : 0.f;
    #pragma unroll
    for (int k = 0; k < 8; k++) {
        const float d2k = __shfl_sync(0xffffffffu, d2, base8 + k);
        if (u < 4) o = fmaf(d2k, Wo[k * 4 + u], o);
    }
    if (u < 4) out[(size_t)e * 4 + u] = o;
}

extern "C" void kernel_launch(void* const* d_in, const int* in_sizes, int n_in,
                              void* d_out, int out_size) {
    const float* past = (const float*)d_in[1];
    const float* fut  = (const float*)d_in[2];
    const float* W1   = (const float*)d_in[3];
    const float* U1   = (const float*)d_in[4];
    const float* b1   = (const float*)d_in[5];
    const float* W2   = (const float*)d_in[6];
    const float* U2   = (const float*)d_in[7];
    const float* b2   = (const float*)d_in[8];
    const float* Wd1  = (const float*)d_in[9];
    const float* bd1  = (const float*)d_in[10];
    const float* Wd2  = (const float*)d_in[11];
    const float* bd2  = (const float*)d_in[12];
    const float* Wo   = (const float*)d_in[13];
    const float* bo   = (const float*)d_in[14];

    LSTM_91122026152229_kernel<<<(BB * HH) / 128, 128>>>(
        past, fut, W1, U1, b1, W2, U2, b2, Wd1, bd1, Wd2, bd2, Wo, bo,
        (float*)d_out);
}

// round 4
// speedup vs baseline: 1.4942x; 1.1358x over previous
#include <cuda_runtime.h>

#define BB 8192
#define TT 256
#define FF 16
#define HH 8
#define FUT 8

__device__ __forceinline__ float tanhm(float x) {
    float y;
    asm("tanh.approx.f32 %0, %1;" : "=f"(y) : "f"(x));
    return y;
}
__device__ __forceinline__ float sigm(float x) {
    // sigmoid(x) = 0.5*tanh(0.5x) + 0.5
    return fmaf(0.5f, tanhm(0.5f * x), 0.5f);
}

__global__ __launch_bounds__(128, 4) void LSTM_91122026152229_kernel(
    const float* __restrict__ past,   // [B,T,F]
    const float* __restrict__ fut,    // [B,FUT]
    const float* __restrict__ W1, const float* __restrict__ U1, const float* __restrict__ b1,
    const float* __restrict__ W2, const float* __restrict__ U2, const float* __restrict__ b2,
    const float* __restrict__ Wd1, const float* __restrict__ bd1,
    const float* __restrict__ Wd2, const float* __restrict__ bd2,
    const float* __restrict__ Wo, const float* __restrict__ bo,
    float* __restrict__ out)          // [B,4]
{
    // Gate-packed weights: sXv[k*8+u] = float4 {w_i, w_f, w_g, w_o}
    __shared__ float4 sW1v[FF * HH];   // 2 KB
    __shared__ float4 sU1v[HH * HH];   // 1 KB
    __shared__ float4 sW2v[HH * HH];   // 1 KB
    __shared__ float4 sU2v[HH * HH];   // 1 KB

    const int tid = threadIdx.x;
    // repack: src i = k*32 + g*8 + u  ->  dst float ((k*8+u)*4 + g)
    for (int i = tid; i < FF * 32; i += 128) {
        int k = i >> 5, r = i & 31, gg = r >> 3, uu = r & 7;
        ((float*)sW1v)[((k * 8 + uu) << 2) + gg] = W1[i];
    }
    for (int i = tid; i < HH * 32; i += 128) {
        int k = i >> 5, r = i & 31, gg = r >> 3, uu = r & 7;
        int o = ((k * 8 + uu) << 2) + gg;
        ((float*)sU1v)[o] = U1[i];
        ((float*)sW2v)[o] = W2[i];
        ((float*)sU2v)[o] = U2[i];
    }
    __syncthreads();

    // 8 threads per batch element; thread owns hidden unit u
    const int g     = blockIdx.x * 128 + tid;
    const int e     = g >> 3;
    const int u     = g & 7;
    const int lane  = tid & 31;
    const int base8 = lane & 24;

    const float4* __restrict__ xp = (const float4*)(past + (size_t)e * (TT * FF));

    const float bi1 = b1[u], bf1 = b1[u + 8], bg1 = b1[u + 16], bq1 = b1[u + 24];
    const float bi2 = b2[u], bf2 = b2[u + 8], bg2 = b2[u + 16], bq2 = b2[u + 24];

    float h1 = 0.f, c1 = 0.f, h2 = 0.f, c2 = 0.f;
    float h1c[8];                      // cached broadcast of h1 (fully unrolled -> regs)
    #pragma unroll
    for (int j = 0; j < 8; j++) h1c[j] = 0.f;

    // prefetch x(0)
    float4 xa = xp[0], xb = xp[1], xc = xp[2], xd = xp[3];

    #pragma unroll 1
    for (int t = 0; t < TT; t++) {
        // prefetch x(t+1) — overlaps with this whole step's compute
        const int tn = (t < TT - 1) ? (t + 1) : t;
        const float4 na = xp[tn * 4 + 0];
        const float4 nb = xp[tn * 4 + 1];
        const float4 nc = xp[tn * 4 + 2];
        const float4 nd = xp[tn * 4 + 3];

        const float xr[16] = { xa.x, xa.y, xa.z, xa.w,  xb.x, xb.y, xb.z, xb.w,
                               xc.x, xc.y, xc.z, xc.w,  xd.x, xd.y, xd.z, xd.w };

        // ---- layer 1 ----
        float zi = bi1, zf = bf1, zg = bg1, zo = bq1;
        #pragma unroll
        for (int k = 0; k < 16; k++) {
            const float4 w = sW1v[k * 8 + u];
            const float xv = xr[k];
            zi = fmaf(xv, w.x, zi);
            zf = fmaf(xv, w.y, zf);
            zg = fmaf(xv, w.z, zg);
            zo = fmaf(xv, w.w, zo);
        }
        #pragma unroll
        for (int k = 0; k < 8; k++) {
            const float4 w = sU1v[k * 8 + u];
            const float hk = h1c[k];
            zi = fmaf(hk, w.x, zi);
            zf = fmaf(hk, w.y, zf);
            zg = fmaf(hk, w.z, zg);
            zo = fmaf(hk, w.w, zo);
        }
        c1 = fmaf(sigm(zf), c1, sigm(zi) * tanhm(zg));
        h1 = sigm(zo) * tanhm(c1);

        // ---- layer 2 (shfl fresh h1 + old h2 interleaved with FMAs; cache h1) ----
        float yi = bi2, yf = bf2, yg = bg2, yo = bq2;
        #pragma unroll
        for (int k = 0; k < 8; k++) {
            const float h1k = __shfl_sync(0xffffffffu, h1, base8 + k);
            const float h2k = __shfl_sync(0xffffffffu, h2, base8 + k);
            const float4 w2 = sW2v[k * 8 + u];
            const float4 u2 = sU2v[k * 8 + u];
            yi = fmaf(h1k, w2.x, fmaf(h2k, u2.x, yi));
            yf = fmaf(h1k, w2.y, fmaf(h2k, u2.y, yf));
            yg = fmaf(h1k, w2.z, fmaf(h2k, u2.z, yg));
            yo = fmaf(h1k, w2.w, fmaf(h2k, u2.w, yo));
            h1c[k] = h1k;              // reuse for next step's layer1
        }
        c2 = fmaf(sigm(yf), c2, sigm(yi) * tanhm(yg));
        h2 = sigm(yo) * tanhm(c2);

        xa = na; xb = nb; xc = nc; xd = nd;
    }

    // ---- MLP head: concat(h2, fut) -> 8 relu -> 8 relu -> 4 ----
    float d1 = bd1[u];
    #pragma unroll
    for (int k = 0; k < 8; k++) {
        const float h2k = __shfl_sync(0xffffffffu, h2, base8 + k);
        d1 = fmaf(h2k, Wd1[k * 8 + u], d1);
    }
    const float* __restrict__ fp = fut + (size_t)e * FUT;
    #pragma unroll
    for (int k = 0; k < 8; k++)
        d1 = fmaf(fp[k], Wd1[(8 + k) * 8 + u], d1);
    d1 = fmaxf(d1, 0.f);

    float d2 = bd2[u];
    #pragma unroll
    for (int k = 0; k < 8; k++) {
        const float d1k = __shfl_sync(0xffffffffu, d1, base8 + k);
        d2 = fmaf(d1k, Wd2[k * 8 + u], d2);
    }
    d2 = fmaxf(d2, 0.f);

    float o = (u < 4) ? bo[u] : 0.f;
    #pragma unroll
    for (int k = 0; k < 8; k++) {
        const float d2k = __shfl_sync(0xffffffffu, d2, base8 + k);
        if (u < 4) o = fmaf(d2k, Wo[k * 4 + u], o);
    }
    if (u < 4) out[(size_t)e * 4 + u] = o;
}

extern "C" void kernel_launch(void* const* d_in, const int* in_sizes, int n_in,
                              void* d_out, int out_size) {
    const float* past = (const float*)d_in[1];
    const float* fut  = (const float*)d_in[2];
    const float* W1   = (const float*)d_in[3];
    const float* U1   = (const float*)d_in[4];
    const float* b1   = (const float*)d_in[5];
    const float* W2   = (const float*)d_in[6];
    const float* U2   = (const float*)d_in[7];
    const float* b2   = (const float*)d_in[8];
    const float* Wd1  = (const float*)d_in[9];
    const float* bd1  = (const float*)d_in[10];
    const float* Wd2  = (const float*)d_in[11];
    const float* bd2  = (const float*)d_in[12];
    const float* Wo   = (const float*)d_in[13];
    const float* bo   = (const float*)d_in[14];

    LSTM_91122026152229_kernel<<<(BB * HH) / 128, 128>>>(
        past, fut, W1, U1, b1, W2, U2, b2, Wd1, bd1, Wd2, bd2, Wo, bo,
        (float*)d_out);
}

// round 5
// speedup vs baseline: 2.1602x; 1.4457x over previous
#include <cuda_runtime.h>

#define BB 8192
#define TT 256
#define FF 16
#define HH 8
#define FUT 8

__device__ __forceinline__ float tanhm(float x) {
    float y;
    asm("tanh.approx.f32 %0, %1;" : "=f"(y) : "f"(x));
    return y;
}
__device__ __forceinline__ float sigm(float x) {
    return fmaf(0.5f, tanhm(0.5f * x), 0.5f);
}

__global__ __launch_bounds__(64) void LSTM_91122026152229_kernel(
    const float* __restrict__ past,   // [B,T,F]
    const float* __restrict__ fut,    // [B,FUT]
    const float* __restrict__ W1, const float* __restrict__ U1, const float* __restrict__ b1,
    const float* __restrict__ W2, const float* __restrict__ U2, const float* __restrict__ b2,
    const float* __restrict__ Wd1, const float* __restrict__ bd1,
    const float* __restrict__ Wd2, const float* __restrict__ bd2,
    const float* __restrict__ Wo, const float* __restrict__ bo,
    float* __restrict__ out)          // [B,4]
{
    // Gate-packed weights: sXv[k*8+u] = float4 {w_i, w_f, w_g, w_o}
    __shared__ float4 sW1v[FF * HH];
    __shared__ float4 sU1v[HH * HH];
    __shared__ float4 sW2v[HH * HH];
    __shared__ float4 sU2v[HH * HH];

    const int tid = threadIdx.x;
    for (int i = tid; i < FF * 32; i += 64) {
        int k = i >> 5, r = i & 31, gg = r >> 3, uu = r & 7;
        ((float*)sW1v)[((k * 8 + uu) << 2) + gg] = W1[i];
    }
    for (int i = tid; i < HH * 32; i += 64) {
        int k = i >> 5, r = i & 31, gg = r >> 3, uu = r & 7;
        int o = ((k * 8 + uu) << 2) + gg;
        ((float*)sU1v)[o] = U1[i];
        ((float*)sW2v)[o] = W2[i];
        ((float*)sU2v)[o] = U2[i];
    }
    __syncthreads();

    // Each thread: unit u for TWO batch elements eA, eB.
    const int g      = blockIdx.x * 64 + tid;
    const int group8 = g >> 3;          // 8-thread group -> element pair
    const int u      = g & 7;
    const int lane   = tid & 31;
    const int base8  = lane & 24;

    const int eA = group8 * 2;
    const int eB = eA + 1;

    const float4* __restrict__ xpA = (const float4*)(past + (size_t)eA * (TT * FF));
    const float4* __restrict__ xpB = (const float4*)(past + (size_t)eB * (TT * FF));

    const float bi1 = b1[u], bf1 = b1[u + 8], bg1 = b1[u + 16], bq1 = b1[u + 24];
    const float bi2 = b2[u], bf2 = b2[u + 8], bg2 = b2[u + 16], bq2 = b2[u + 24];

    float h1A = 0.f, c1A = 0.f, h2A = 0.f, c2A = 0.f;
    float h1B = 0.f, c1B = 0.f, h2B = 0.f, c2B = 0.f;
    float h1cA[8], h1cB[8];
    #pragma unroll
    for (int j = 0; j < 8; j++) { h1cA[j] = 0.f; h1cB[j] = 0.f; }

    // prefetch x(0) for both elements
    float4 a0 = xpA[0], a1 = xpA[1], a2 = xpA[2], a3 = xpA[3];
    float4 b0 = xpB[0], b1r = xpB[1], b2r = xpB[2], b3 = xpB[3];

    #pragma unroll 1
    for (int t = 0; t < TT; t++) {
        const int tn = (t < TT - 1) ? (t + 1) : t;
        const float4 nA0 = xpA[tn * 4 + 0];
        const float4 nA1 = xpA[tn * 4 + 1];
        const float4 nA2 = xpA[tn * 4 + 2];
        const float4 nA3 = xpA[tn * 4 + 3];
        const float4 nB0 = xpB[tn * 4 + 0];
        const float4 nB1 = xpB[tn * 4 + 1];
        const float4 nB2 = xpB[tn * 4 + 2];
        const float4 nB3 = xpB[tn * 4 + 3];

        const float xrA[16] = { a0.x,a0.y,a0.z,a0.w, a1.x,a1.y,a1.z,a1.w,
                                a2.x,a2.y,a2.z,a2.w, a3.x,a3.y,a3.z,a3.w };
        const float xrB[16] = { b0.x,b0.y,b0.z,b0.w, b1r.x,b1r.y,b1r.z,b1r.w,
                                b2r.x,b2r.y,b2r.z,b2r.w, b3.x,b3.y,b3.z,b3.w };

        // ---- layer 1, both elements share each weight load ----
        float ziA = bi1, zfA = bf1, zgA = bg1, zoA = bq1;
        float ziB = bi1, zfB = bf1, zgB = bg1, zoB = bq1;
        #pragma unroll
        for (int k = 0; k < 16; k++) {
            const float4 w = sW1v[k * 8 + u];
            const float xA = xrA[k], xB = xrB[k];
            ziA = fmaf(xA, w.x, ziA);  ziB = fmaf(xB, w.x, ziB);
            zfA = fmaf(xA, w.y, zfA);  zfB = fmaf(xB, w.y, zfB);
            zgA = fmaf(xA, w.z, zgA);  zgB = fmaf(xB, w.z, zgB);
            zoA = fmaf(xA, w.w, zoA);  zoB = fmaf(xB, w.w, zoB);
        }
        #pragma unroll
        for (int k = 0; k < 8; k++) {
            const float4 w = sU1v[k * 8 + u];
            const float hA = h1cA[k], hB = h1cB[k];
            ziA = fmaf(hA, w.x, ziA);  ziB = fmaf(hB, w.x, ziB);
            zfA = fmaf(hA, w.y, zfA);  zfB = fmaf(hB, w.y, zfB);
            zgA = fmaf(hA, w.z, zgA);  zgB = fmaf(hB, w.z, zgB);
            zoA = fmaf(hA, w.w, zoA);  zoB = fmaf(hB, w.w, zoB);
        }
        c1A = fmaf(sigm(zfA), c1A, sigm(ziA) * tanhm(zgA));
        h1A = sigm(zoA) * tanhm(c1A);
        c1B = fmaf(sigm(zfB), c1B, sigm(ziB) * tanhm(zgB));
        h1B = sigm(zoB) * tanhm(c1B);

        // ---- layer 2 ----
        float yiA = bi2, yfA = bf2, ygA = bg2, yoA = bq2;
        float yiB = bi2, yfB = bf2, ygB = bg2, yoB = bq2;
        #pragma unroll
        for (int k = 0; k < 8; k++) {
            const float h1kA = __shfl_sync(0xffffffffu, h1A, base8 + k);
            const float h1kB = __shfl_sync(0xffffffffu, h1B, base8 + k);
            const float h2kA = __shfl_sync(0xffffffffu, h2A, base8 + k);
            const float h2kB = __shfl_sync(0xffffffffu, h2B, base8 + k);
            const float4 w2 = sW2v[k * 8 + u];
            const float4 u2 = sU2v[k * 8 + u];
            yiA = fmaf(h1kA, w2.x, fmaf(h2kA, u2.x, yiA));
            yiB = fmaf(h1kB, w2.x, fmaf(h2kB, u2.x, yiB));
            yfA = fmaf(h1kA, w2.y, fmaf(h2kA, u2.y, yfA));
            yfB = fmaf(h1kB, w2.y, fmaf(h2kB, u2.y, yfB));
            ygA = fmaf(h1kA, w2.z, fmaf(h2kA, u2.z, ygA));
            ygB = fmaf(h1kB, w2.z, fmaf(h2kB, u2.z, ygB));
            yoA = fmaf(h1kA, w2.w, fmaf(h2kA, u2.w, yoA));
            yoB = fmaf(h1kB, w2.w, fmaf(h2kB, u2.w, yoB));
            h1cA[k] = h1kA;
            h1cB[k] = h1kB;
        }
        c2A = fmaf(sigm(yfA), c2A, sigm(yiA) * tanhm(ygA));
        h2A = sigm(yoA) * tanhm(c2A);
        c2B = fmaf(sigm(yfB), c2B, sigm(yiB) * tanhm(ygB));
        h2B = sigm(yoB) * tanhm(c2B);

        a0 = nA0; a1 = nA1; a2 = nA2; a3 = nA3;
        b0 = nB0; b1r = nB1; b2r = nB2; b3 = nB3;
    }

    // ---- MLP head for both elements ----
    float d1A = bd1[u], d1B = bd1[u];
    #pragma unroll
    for (int k = 0; k < 8; k++) {
        const float wk = Wd1[k * 8 + u];
        const float h2kA = __shfl_sync(0xffffffffu, h2A, base8 + k);
        const float h2kB = __shfl_sync(0xffffffffu, h2B, base8 + k);
        d1A = fmaf(h2kA, wk, d1A);
        d1B = fmaf(h2kB, wk, d1B);
    }
    const float* __restrict__ fpA = fut + (size_t)eA * FUT;
    const float* __restrict__ fpB = fut + (size_t)eB * FUT;
    #pragma unroll
    for (int k = 0; k < 8; k++) {
        const float wk = Wd1[(8 + k) * 8 + u];
        d1A = fmaf(fpA[k], wk, d1A);
        d1B = fmaf(fpB[k], wk, d1B);
    }
    d1A = fmaxf(d1A, 0.f);
    d1B = fmaxf(d1B, 0.f);

    float d2A = bd2[u], d2B = bd2[u];
    #pragma unroll
    for (int k = 0; k < 8; k++) {
        const float wk = Wd2[k * 8 + u];
        const float d1kA = __shfl_sync(0xffffffffu, d1A, base8 + k);
        const float d1kB = __shfl_sync(0xffffffffu, d1B, base8 + k);
        d2A = fmaf(d1kA, wk, d2A);
        d2B = fmaf(d1kB, wk, d2B);
    }
    d2A = fmaxf(d2A, 0.f);
    d2B = fmaxf(d2B, 0.f);

    float oA = (u < 4) ? bo[u] : 0.f;
    float oB = oA;
    #pragma unroll
    for (int k = 0; k < 8; k++) {
        const float wk = (u < 4) ? Wo[k * 4 + u] : 0.f;
        const float d2kA = __shfl_sync(0xffffffffu, d2A, base8 + k);
        const float d2kB = __shfl_sync(0xffffffffu, d2B, base8 + k);
        oA = fmaf(d2kA, wk, oA);
        oB = fmaf(d2kB, wk, oB);
    }
    if (u < 4) {
        out[(size_t)eA * 4 + u] = oA;
        out[(size_t)eB * 4 + u] = oB;
    }
}

extern "C" void kernel_launch(void* const* d_in, const int* in_sizes, int n_in,
                              void* d_out, int out_size) {
    const float* past = (const float*)d_in[1];
    const float* fut  = (const float*)d_in[2];
    const float* W1   = (const float*)d_in[3];
    const float* U1   = (const float*)d_in[4];
    const float* b1   = (const float*)d_in[5];
    const float* W2   = (const float*)d_in[6];
    const float* U2   = (const float*)d_in[7];
    const float* b2   = (const float*)d_in[8];
    const float* Wd1  = (const float*)d_in[9];
    const float* bd1  = (const float*)d_in[10];
    const float* Wd2  = (const float*)d_in[11];
    const float* bd2  = (const float*)d_in[12];
    const float* Wo   = (const float*)d_in[13];
    const float* bo   = (const float*)d_in[14];

    // 32768 threads: 8 per element-pair (2 elements per thread)
    LSTM_91122026152229_kernel<<<(BB * HH / 2) / 64, 64>>>(
        past, fut, W1, U1, b1, W2, U2, b2, Wd1, bd1, Wd2, bd2, Wo, bo,
        (float*)d_out);
}